// round 8
// baseline (speedup 1.0000x reference)
#include <cuda_runtime.h>
#include <cuda_bf16.h>
#include <cstdint>

// SAGAN self-attention, B=8, C=64, N=4096, Ck=8.
// out = gamma * (h @ softmax_n(f^T g)) + x
// Flash streaming over n, split 4 ways over n (partials combined in kernel 3).
// gemm1 = tf32 m16n8k8 (f pre-permuted to B-frag order), gemm2 = bf16 m16n8k16
// with C->A pack trick and ldmatrix.x4 B-frags. No max-subtraction
// (|s|*log2e <= ~25, exp2 cannot overflow fp32); log2e folded into g.

#define Bb 8
#define Cc 64
#define Nn 4096
#define CK 8
#define MT 128
#define NT 64
#define NSPLIT 4
#define NHALF (Nn / NSPLIT)
#define NITER (NHALF / NT)
#define LOG2E 1.44269504088896340736f

// Scratch (allocation-free rule: __device__ globals)
__device__ float    d_gbuf[Bb * Nn * CK];             // [b][m][k] tf32 * log2e
__device__ float    d_fperm[Bb * (Nn / 16) * 32 * 4]; // B-frag order per 16-n group
__device__ uint16_t d_hbuf[Bb * Cc * Nn];             // bf16 [b][c][n]
__device__ float    d_Opart[NSPLIT * Bb * Nn * Cc];   // [part][b][m][c]
__device__ float    d_Lpart[NSPLIT * Bb * Nn];        // [part][b][m]

// ---------------- helpers ----------------
__device__ __forceinline__ uint32_t smem_u32(const void* p) {
    uint32_t a;
    asm("{ .reg .u64 t; cvta.to.shared.u64 t, %1; cvt.u32.u64 %0, t; }" : "=r"(a) : "l"(p));
    return a;
}
__device__ __forceinline__ float f2tf(float x) {
    uint32_t r;
    asm("cvt.rna.tf32.f32 %0, %1;" : "=r"(r) : "f"(x));
    return __uint_as_float(r);
}
__device__ __forceinline__ float ex2(float x) {
    float r;
    asm("ex2.approx.f32 %0, %1;" : "=f"(r) : "f"(x));
    return r;
}
__device__ __forceinline__ uint32_t packbf(float lo, float hi) {
    uint32_t d;
    asm("cvt.rn.bf16x2.f32 %0, %1, %2;" : "=r"(d) : "f"(hi), "f"(lo));
    return d;
}

#define MMA_TF32(d, a0, a1, a2, a3, b0, b1)                                   \
    asm volatile("mma.sync.aligned.m16n8k8.row.col.f32.tf32.tf32.f32 "        \
                 "{%0,%1,%2,%3}, {%4,%5,%6,%7}, {%8,%9}, {%0,%1,%2,%3};"      \
                 : "+f"((d)[0]), "+f"((d)[1]), "+f"((d)[2]), "+f"((d)[3])     \
                 : "r"(a0), "r"(a1), "r"(a2), "r"(a3), "r"(b0), "r"(b1))

#define MMA_BF16(d, a0, a1, a2, a3, b0, b1)                                   \
    asm volatile("mma.sync.aligned.m16n8k16.row.col.f32.bf16.bf16.f32 "       \
                 "{%0,%1,%2,%3}, {%4,%5,%6,%7}, {%8,%9}, {%0,%1,%2,%3};"      \
                 : "+f"((d)[0]), "+f"((d)[1]), "+f"((d)[2]), "+f"((d)[3])     \
                 : "r"(a0), "r"(a1), "r"(a2), "r"(a3), "r"(b0), "r"(b1))

#define LDMX4(r0, r1, r2, r3, addr)                                           \
    asm volatile("ldmatrix.sync.aligned.m8n8.x4.shared.b16 {%0,%1,%2,%3}, [%4];" \
                 : "=r"(r0), "=r"(r1), "=r"(r2), "=r"(r3) : "r"(addr))

#define CP16(dst, src) \
    asm volatile("cp.async.cg.shared.global [%0], [%1], 16;" :: "r"(dst), "l"(src))
#define CP_COMMIT() asm volatile("cp.async.commit_group;" ::: "memory")
#define CP_WAIT1()  asm volatile("cp.async.wait_group 1;" ::: "memory")

// ---------------------------------------------------------------------------
// Kernel 1: projections, split-K x4 for latency hiding (27.7 warps/SM demand).
//   256 threads = 64 pixels x 4 K-quarters. Thread computes 80 partial dots
//   over its 16 channels; quad-combine via shfl_xor(1),(2).
//   w in smem [r][kq][20] (quad-broadcast float4, conflict-free).
//   f B-frag-permuted, g *log2e tf32, h bf16 [b][c][n].
// ---------------------------------------------------------------------------
__global__ __launch_bounds__(256) void proj_kernel(
    const float* __restrict__ x,
    const float* __restrict__ wq,
    const float* __restrict__ wk,
    const float* __restrict__ wv)
{
    __shared__ float w_s[80 * 4 * 20];
    __shared__ float f_stage[8][64];
    const int b   = blockIdx.y;
    const int n0  = blockIdx.x * 64;
    const int tid = threadIdx.x;
    const int p   = tid >> 2;       // pixel 0..63
    const int kh  = tid & 3;        // K quarter
    const int n   = n0 + p;

    for (int e = tid; e < 80 * 64; e += 256) {
        int r = e >> 6, cc = e & 63;
        float v;
        if (r < 8)       v = wq[r * Cc + cc];
        else if (r < 16) v = wk[(r - 8) * Cc + cc];
        else             v = wv[(r - 16) * Cc + cc];
        w_s[(r * 4 + (cc >> 4)) * 20 + (cc & 15)] = v;
    }
    __syncthreads();

    float xr[16];
#pragma unroll
    for (int c = 0; c < 16; c++) xr[c] = x[(b * Cc + kh * 16 + c) * Nn + n];

    for (int rg = 0; rg < 10; rg++) {
        float acc[8];
#pragma unroll
        for (int j = 0; j < 8; j++) {
            const float4* wr = (const float4*)&w_s[((rg * 8 + j) * 4 + kh) * 20];
            float a = 0.f;
#pragma unroll
            for (int q = 0; q < 4; q++) {
                float4 w4 = wr[q];
                a += w4.x * xr[4 * q + 0];
                a += w4.y * xr[4 * q + 1];
                a += w4.z * xr[4 * q + 2];
                a += w4.w * xr[4 * q + 3];
            }
            acc[j] = a;
        }
#pragma unroll
        for (int j = 0; j < 8; j++) {
            acc[j] += __shfl_xor_sync(0xffffffffu, acc[j], 1);
            acc[j] += __shfl_xor_sync(0xffffffffu, acc[j], 2);
        }

        if (rg == 0) {
            if (kh == 0)
#pragma unroll
                for (int j = 0; j < 8; j++) f_stage[j][p] = f2tf(acc[j]);
        } else if (rg == 1) {
            if (kh == 0) {
                float4* gp = (float4*)(d_gbuf + (size_t)(b * Nn + n) * CK);
                gp[0] = make_float4(f2tf(acc[0] * LOG2E), f2tf(acc[1] * LOG2E),
                                    f2tf(acc[2] * LOG2E), f2tf(acc[3] * LOG2E));
                gp[1] = make_float4(f2tf(acc[4] * LOG2E), f2tf(acc[5] * LOG2E),
                                    f2tf(acc[6] * LOG2E), f2tf(acc[7] * LOG2E));
            }
        } else {
            // h output channel c = (rg-2)*8 + j; row j written by quad-lane j&3
            const int c0 = (rg - 2) * 8;
#pragma unroll
            for (int j = 0; j < 8; j++) {
                if ((j & 3) == kh) {
                    __nv_bfloat16 hv = __float2bfloat16(acc[j]);
                    d_hbuf[(size_t)(b * Cc + c0 + j) * Nn + n] = *(uint16_t*)&hv;
                }
            }
        }
    }
    __syncthreads();

    // permuted f writeout: 4 groups of 16 pixels, 32 lanes each (threads 0..127)
    if (tid < 128) {
        int t = tid >> 5, l = tid & 31, g = l >> 2, tg = l & 3;
        int nl = 16 * t + g;
        float4 v = make_float4(f_stage[tg][nl],     f_stage[tg + 4][nl],
                               f_stage[tg][nl + 8], f_stage[tg + 4][nl + 8]);
        ((float4*)d_fperm)[(size_t)(b * (Nn / 16) + blockIdx.x * 4 + t) * 32 + l] = v;
    }
}

// ---------------------------------------------------------------------------
// Kernel 2: warp-mma flash attention over one n-quarter.
//   128 threads (4 warps), warp = 32 m (2 m16 frags), MT=128, NT=64.
// ---------------------------------------------------------------------------
__global__ __launch_bounds__(128) void attn_mma_kernel()
{
    __shared__ float4   fsp[2][4][32];       // permuted f
    __shared__ uint16_t hs[2][Cc][72];       // h [c][n] bf16, stride 72 (144B)

    const int tid  = threadIdx.x;
    const int w    = tid >> 5;
    const int lane = tid & 31;
    const int g    = lane >> 2;
    const int tg   = lane & 3;
    const int b    = blockIdx.y;
    const int m0   = blockIdx.x * MT;
    const int part = blockIdx.z;
    const int nbase = part * NHALF;

    const uint32_t fsb = smem_u32(&fsp[0][0][0]);
    const uint32_t hsb = smem_u32(&hs[0][0][0]);

    uint32_t gfr[2][4];
#pragma unroll
    for (int mf = 0; mf < 2; mf++) {
        const int mb = m0 + w * 32 + mf * 16;
        const float* gp = d_gbuf + (size_t)(b * Nn) * CK;
        gfr[mf][0] = __float_as_uint(gp[(mb + g) * CK + tg]);
        gfr[mf][1] = __float_as_uint(gp[(mb + 8 + g) * CK + tg]);
        gfr[mf][2] = __float_as_uint(gp[(mb + g) * CK + tg + 4]);
        gfr[mf][3] = __float_as_uint(gp[(mb + 8 + g) * CK + tg + 4]);
    }

    float O[2][8][4];
#pragma unroll
    for (int mf = 0; mf < 2; mf++)
#pragma unroll
        for (int cf = 0; cf < 8; cf++)
#pragma unroll
            for (int j = 0; j < 4; j++) O[mf][cf][j] = 0.f;
    float Ls[2][2] = {{0.f, 0.f}, {0.f, 0.f}};

    auto issue_tile = [&](int it) {
        const int p  = it & 1;
        const int n0 = nbase + it * NT;
        {   // f: 4 groups x 32 lanes = 128 cp16
            int t = tid >> 5, l = tid & 31;
            CP16(fsb + (uint32_t)((p * 128 + t * 32 + l) * 16),
                 d_fperm + ((size_t)(b * (Nn / 16) + (n0 >> 4) + t) * 32 + l) * 4);
        }
#pragma unroll
        for (int k = 0; k < 4; k++) {   // h: 64 rows x 8 chunks of 16B
            int e = tid + k * 128;
            int c = e >> 3, ch = e & 7;
            CP16(hsb + (uint32_t)(((p * Cc + c) * 72 + ch * 8) * 2),
                 d_hbuf + (size_t)(b * Cc + c) * Nn + n0 + ch * 8);
        }
    };

    issue_tile(0); CP_COMMIT();
    issue_tile(1); CP_COMMIT();

    const uint32_t lm_row = ((lane >> 4) & 1) * 8 + (lane & 7);
    const uint32_t lm_col = ((lane >> 3) & 1) * 8;

    for (int it = 0; it < NITER; ++it) {
        const int p = it & 1;
        CP_WAIT1();
        __syncthreads();

#pragma unroll
        for (int t = 0; t < NT / 16; t++) {
            float4 fv = fsp[p][t][lane];
            uint32_t fb0 = __float_as_uint(fv.x), fb1 = __float_as_uint(fv.y);
            uint32_t fb2 = __float_as_uint(fv.z), fb3 = __float_as_uint(fv.w);

            float c00[4] = {0, 0, 0, 0}, c01[4] = {0, 0, 0, 0};
            float c10[4] = {0, 0, 0, 0}, c11[4] = {0, 0, 0, 0};
            MMA_TF32(c00, gfr[0][0], gfr[0][1], gfr[0][2], gfr[0][3], fb0, fb1);
            MMA_TF32(c01, gfr[0][0], gfr[0][1], gfr[0][2], gfr[0][3], fb2, fb3);
            MMA_TF32(c10, gfr[1][0], gfr[1][1], gfr[1][2], gfr[1][3], fb0, fb1);
            MMA_TF32(c11, gfr[1][0], gfr[1][1], gfr[1][2], gfr[1][3], fb2, fb3);

            uint32_t pa[2][4];
#pragma unroll
            for (int mf = 0; mf < 2; mf++) {
                float* c0 = mf ? c10 : c00;
                float* c1 = mf ? c11 : c01;
                float p00 = ex2(c0[0]), p01 = ex2(c0[1]), p02 = ex2(c0[2]), p03 = ex2(c0[3]);
                float p10 = ex2(c1[0]), p11 = ex2(c1[1]), p12 = ex2(c1[2]), p13 = ex2(c1[3]);
                Ls[mf][0] += (p00 + p01) + (p10 + p11);
                Ls[mf][1] += (p02 + p03) + (p12 + p13);
                pa[mf][0] = packbf(p00, p01);
                pa[mf][1] = packbf(p02, p03);
                pa[mf][2] = packbf(p10, p11);
                pa[mf][3] = packbf(p12, p13);
            }

#pragma unroll
            for (int p2 = 0; p2 < 4; p2++) {
                uint32_t r0, r1, r2, r3;
                uint32_t addr = hsb + ((p * Cc + 16 * p2 + lm_row) * 72 + 16 * t + lm_col) * 2;
                LDMX4(r0, r1, r2, r3, addr);
                const int cf = 2 * p2;
                MMA_BF16(O[0][cf],     pa[0][0], pa[0][1], pa[0][2], pa[0][3], r0, r1);
                MMA_BF16(O[1][cf],     pa[1][0], pa[1][1], pa[1][2], pa[1][3], r0, r1);
                MMA_BF16(O[0][cf + 1], pa[0][0], pa[0][1], pa[0][2], pa[0][3], r2, r3);
                MMA_BF16(O[1][cf + 1], pa[1][0], pa[1][1], pa[1][2], pa[1][3], r2, r3);
            }
        }
        __syncthreads();
        if (it + 2 < NITER) issue_tile(it + 2);
        CP_COMMIT();
    }

    // quad-reduce row sums
#pragma unroll
    for (int mf = 0; mf < 2; mf++)
#pragma unroll
        for (int hh = 0; hh < 2; hh++) {
            float v = Ls[mf][hh];
            v += __shfl_xor_sync(0xffffffffu, v, 1);
            v += __shfl_xor_sync(0xffffffffu, v, 2);
            Ls[mf][hh] = v;
        }

    // write partials
    const size_t base = (size_t)(part * Bb + b) * Nn;
#pragma unroll
    for (int mf = 0; mf < 2; mf++) {
        const int r = m0 + w * 32 + mf * 16 + g;
#pragma unroll
        for (int cf = 0; cf < 8; cf++) {
            const int c = cf * 8 + 2 * tg;
            *(float2*)&d_Opart[(base + r) * Cc + c]     = make_float2(O[mf][cf][0], O[mf][cf][1]);
            *(float2*)&d_Opart[(base + r + 8) * Cc + c] = make_float2(O[mf][cf][2], O[mf][cf][3]);
        }
        if (tg == 0) {
            d_Lpart[base + r]     = Ls[mf][0];
            d_Lpart[base + r + 8] = Ls[mf][1];
        }
    }
}

// ---------------------------------------------------------------------------
// Kernel 3: combine 4 parts + residual.  out[b][c][m] = ga*sum(O)/sum(L) + x
// ---------------------------------------------------------------------------
__global__ __launch_bounds__(256) void combine_kernel(
    const float* __restrict__ x,
    const float* __restrict__ gamma,
    float* __restrict__ out)
{
    __shared__ float sL[64];
    __shared__ float s[64][65];
    const int b   = blockIdx.y;
    const int m0  = blockIdx.x * 64;
    const int tid = threadIdx.x;
    const float ga = gamma[0];

    if (tid < 64) {
        float L = 0.f;
#pragma unroll
        for (int hh = 0; hh < NSPLIT; hh++)
            L += d_Lpart[(size_t)(hh * Bb + b) * Nn + m0 + tid];
        sL[tid] = ga / L;
    }
    __syncthreads();

#pragma unroll
    for (int k = 0; k < 4; k++) {
        int e = tid + k * 256;
        int ml = e >> 4, cq = e & 15;
        float4 a = make_float4(0.f, 0.f, 0.f, 0.f);
#pragma unroll
        for (int hh = 0; hh < NSPLIT; hh++) {
            const float4 v = *(const float4*)&d_Opart[((size_t)(hh * Bb + b) * Nn + m0 + ml) * Cc + cq * 4];
            a.x += v.x; a.y += v.y; a.z += v.z; a.w += v.w;
        }
        const float inv = sL[ml];
        s[cq * 4 + 0][ml] = a.x * inv;
        s[cq * 4 + 1][ml] = a.y * inv;
        s[cq * 4 + 2][ml] = a.z * inv;
        s[cq * 4 + 3][ml] = a.w * inv;
    }
    __syncthreads();

#pragma unroll
    for (int k = 0; k < 4; k++) {
        int e = tid + k * 256;
        int c = e >> 4, mq = e & 15;
        int gi = (b * Cc + c) * Nn + m0 + mq * 4;
        float4 xv = *(const float4*)&x[gi];
        float4 o;
        o.x = s[c][mq * 4 + 0] + xv.x;
        o.y = s[c][mq * 4 + 1] + xv.y;
        o.z = s[c][mq * 4 + 2] + xv.z;
        o.w = s[c][mq * 4 + 3] + xv.w;
        *(float4*)&out[gi] = o;
    }
}

// ---------------------------------------------------------------------------
extern "C" void kernel_launch(void* const* d_in, const int* in_sizes, int n_in,
                              void* d_out, int out_size)
{
    const float* x     = (const float*)d_in[0];
    const float* wq    = (const float*)d_in[1];
    const float* wk    = (const float*)d_in[2];
    const float* wv    = (const float*)d_in[3];
    const float* gamma = (const float*)d_in[4];
    float* out = (float*)d_out;
    (void)in_sizes; (void)n_in; (void)out_size;

    proj_kernel<<<dim3(Nn / 64, Bb), 256>>>(x, wq, wk, wv);
    attn_mma_kernel<<<dim3(Nn / MT, Bb, NSPLIT), 128>>>();
    combine_kernel<<<dim3(Nn / 64, Bb), 256>>>(x, gamma, out);
}

// round 9
// speedup vs baseline: 1.2503x; 1.2503x over previous
#include <cuda_runtime.h>
#include <cuda_bf16.h>
#include <cstdint>

// SAGAN self-attention, B=8, C=64, N=4096, Ck=8.
// out = gamma * (h @ softmax_n(f^T g)) + x
// All three GEMMs on tensor cores (mma.sync, sm_103 baseline PTX):
//   proj: f/g/h = W x   (tf32 m16n8k8, W in A-frags — kills SIMT weight-LDS wall)
//   attn: gemm1 tf32, gemm2 bf16 with C->A pack, flash over n, NSPLIT=4.
// No max-subtraction (|s|*log2e <= ~25); log2e folded into wk.

#define Bb 8
#define Cc 64
#define Nn 4096
#define CK 8
#define MT 128
#define NT 64
#define NSPLIT 4
#define NHALF (Nn / NSPLIT)
#define NITER (NHALF / NT)
#define LOG2E 1.44269504088896340736f

// Scratch (allocation-free rule: __device__ globals)
__device__ float    d_gbuf[Bb * Nn * CK];             // [b][m][k] tf32 * log2e
__device__ float    d_fperm[Bb * (Nn / 16) * 32 * 4]; // B-frag order per 16-n group
__device__ uint16_t d_hbuf[Bb * Cc * Nn];             // bf16 [b][c][n]
__device__ float    d_Opart[NSPLIT * Bb * Nn * Cc];   // [part][b][m][c]
__device__ float    d_Lpart[NSPLIT * Bb * Nn];        // [part][b][m]

// ---------------- helpers ----------------
__device__ __forceinline__ uint32_t smem_u32(const void* p) {
    uint32_t a;
    asm("{ .reg .u64 t; cvta.to.shared.u64 t, %1; cvt.u32.u64 %0, t; }" : "=r"(a) : "l"(p));
    return a;
}
__device__ __forceinline__ float f2tf(float x) {
    uint32_t r;
    asm("cvt.rna.tf32.f32 %0, %1;" : "=r"(r) : "f"(x));
    return __uint_as_float(r);
}
__device__ __forceinline__ float ex2(float x) {
    float r;
    asm("ex2.approx.f32 %0, %1;" : "=f"(r) : "f"(x));
    return r;
}
__device__ __forceinline__ uint32_t packbf(float lo, float hi) {
    uint32_t d;
    asm("cvt.rn.bf16x2.f32 %0, %1, %2;" : "=r"(d) : "f"(hi), "f"(lo));
    return d;
}

#define MMA_TF32(d, a0, a1, a2, a3, b0, b1)                                   \
    asm volatile("mma.sync.aligned.m16n8k8.row.col.f32.tf32.tf32.f32 "        \
                 "{%0,%1,%2,%3}, {%4,%5,%6,%7}, {%8,%9}, {%0,%1,%2,%3};"      \
                 : "+f"((d)[0]), "+f"((d)[1]), "+f"((d)[2]), "+f"((d)[3])     \
                 : "r"(a0), "r"(a1), "r"(a2), "r"(a3), "r"(b0), "r"(b1))

#define MMA_BF16(d, a0, a1, a2, a3, b0, b1)                                   \
    asm volatile("mma.sync.aligned.m16n8k16.row.col.f32.bf16.bf16.f32 "       \
                 "{%0,%1,%2,%3}, {%4,%5,%6,%7}, {%8,%9}, {%0,%1,%2,%3};"      \
                 : "+f"((d)[0]), "+f"((d)[1]), "+f"((d)[2]), "+f"((d)[3])     \
                 : "r"(a0), "r"(a1), "r"(a2), "r"(a3), "r"(b0), "r"(b1))

#define LDMX4(r0, r1, r2, r3, addr)                                           \
    asm volatile("ldmatrix.sync.aligned.m8n8.x4.shared.b16 {%0,%1,%2,%3}, [%4];" \
                 : "=r"(r0), "=r"(r1), "=r"(r2), "=r"(r3) : "r"(addr))

#define CP16(dst, src) \
    asm volatile("cp.async.cg.shared.global [%0], [%1], 16;" :: "r"(dst), "l"(src))
#define CP_COMMIT() asm volatile("cp.async.commit_group;" ::: "memory")
#define CP_WAIT1()  asm volatile("cp.async.wait_group 1;" ::: "memory")

// ---------------------------------------------------------------------------
// Kernel 1: projections via tf32 mma.
//   Block = 64 pixels, 128 threads (4 warps).
//   Warp w: (a) [wq;wk] m16 A-frag x its 16 px -> f rows 0-7, g rows 8-15;
//           (b) wv rows 16w..16w+15 x all 64 px -> h (bf16 store).
// ---------------------------------------------------------------------------
__global__ __launch_bounds__(128) void proj_kernel(
    const float* __restrict__ x,
    const float* __restrict__ wq,
    const float* __restrict__ wk,
    const float* __restrict__ wv)
{
    __shared__ float wqk_s[16][68];   // rows 0-7 wq, 8-15 wk*log2e (tf32)
    __shared__ float wv_s[64][68];    // wv (tf32)
    __shared__ float xs[64][72];      // x tile [ch][px] (tf32)
    __shared__ float f_st[8][68];     // f staging [row][px]
    __shared__ float g_st[64][8];     // g staging [px][row]

    const int b    = blockIdx.y;
    const int n0   = blockIdx.x * 64;
    const int tid  = threadIdx.x;
    const int w    = tid >> 5;
    const int lane = tid & 31;
    const int g    = lane >> 2;   // 0..7
    const int tg   = lane & 3;    // 0..3

    for (int e = tid; e < 16 * 64; e += 128) {
        int r = e >> 6, c = e & 63;
        float v = (r < 8) ? wq[r * Cc + c] : wk[(r - 8) * Cc + c] * LOG2E;
        wqk_s[r][c] = f2tf(v);
    }
    for (int e = tid; e < 64 * 64; e += 128) {
        int r = e >> 6, c = e & 63;
        wv_s[r][c] = f2tf(wv[r * Cc + c]);
    }
    for (int e = tid; e < 64 * 16; e += 128) {
        int ch = e >> 4, q = e & 15;
        float4 v = *(const float4*)&x[(size_t)(b * Cc + ch) * Nn + n0 + q * 4];
        xs[ch][q * 4 + 0] = f2tf(v.x);
        xs[ch][q * 4 + 1] = f2tf(v.y);
        xs[ch][q * 4 + 2] = f2tf(v.z);
        xs[ch][q * 4 + 3] = f2tf(v.w);
    }
    __syncthreads();

    // ---- f/g: one m16 A-frag ([wq;wk]), warp's 16 px ----
    {
        uint32_t aq[8][4];
#pragma unroll
        for (int ks = 0; ks < 8; ks++) {
            aq[ks][0] = __float_as_uint(wqk_s[g][8 * ks + tg]);
            aq[ks][1] = __float_as_uint(wqk_s[g + 8][8 * ks + tg]);
            aq[ks][2] = __float_as_uint(wqk_s[g][8 * ks + tg + 4]);
            aq[ks][3] = __float_as_uint(wqk_s[g + 8][8 * ks + tg + 4]);
        }
#pragma unroll
        for (int t2 = 0; t2 < 2; t2++) {
            const int px0 = 16 * w + 8 * t2;
            float C[4] = {0.f, 0.f, 0.f, 0.f};
#pragma unroll
            for (int ks = 0; ks < 8; ks++) {
                uint32_t b0 = __float_as_uint(xs[8 * ks + tg][px0 + g]);
                uint32_t b1 = __float_as_uint(xs[8 * ks + tg + 4][px0 + g]);
                MMA_TF32(C, aq[ks][0], aq[ks][1], aq[ks][2], aq[ks][3], b0, b1);
            }
            // stage f (rows 0-7): C[0],C[1] = f[g][px0+2tg, +1]
            f_st[g][px0 + 2 * tg]     = f2tf(C[0]);
            f_st[g][px0 + 2 * tg + 1] = f2tf(C[1]);
            // stage g (rows 8-15): C[2],C[3] = g[g][px0+2tg, +1] -> [px][row]
            g_st[px0 + 2 * tg][g]     = f2tf(C[2]);
            g_st[px0 + 2 * tg + 1][g] = f2tf(C[3]);
        }
        __syncwarp();

        // d_fperm: this warp's 16-px group, B-frag float4 per lane
        {
            float4 v = make_float4(f_st[tg][16 * w + g],     f_st[tg + 4][16 * w + g],
                                   f_st[tg][16 * w + 8 + g], f_st[tg + 4][16 * w + 8 + g]);
            ((float4*)d_fperm)[(size_t)(b * (Nn / 16) + (n0 >> 4) + w) * 32 + lane] = v;
        }
        // d_gbuf: [m][k], 16 px x 2 float4
        {
            int px = lane >> 1, hf = lane & 1;
            float4 gv = *(float4*)&g_st[16 * w + px][4 * hf];
            *(float4*)&d_gbuf[(size_t)(b * Nn + n0 + 16 * w + px) * CK + 4 * hf] = gv;
        }
    }

    // ---- h: wv rows 16w..16w+15 x all 64 px ----
    {
        uint32_t av[8][4];
#pragma unroll
        for (int ks = 0; ks < 8; ks++) {
            av[ks][0] = __float_as_uint(wv_s[16 * w + g][8 * ks + tg]);
            av[ks][1] = __float_as_uint(wv_s[16 * w + g + 8][8 * ks + tg]);
            av[ks][2] = __float_as_uint(wv_s[16 * w + g][8 * ks + tg + 4]);
            av[ks][3] = __float_as_uint(wv_s[16 * w + g + 8][8 * ks + tg + 4]);
        }
#pragma unroll
        for (int j = 0; j < 8; j++) {
            float C[4] = {0.f, 0.f, 0.f, 0.f};
#pragma unroll
            for (int ks = 0; ks < 8; ks++) {
                uint32_t b0 = __float_as_uint(xs[8 * ks + tg][8 * j + g]);
                uint32_t b1 = __float_as_uint(xs[8 * ks + tg + 4][8 * j + g]);
                MMA_TF32(C, av[ks][0], av[ks][1], av[ks][2], av[ks][3], b0, b1);
            }
            const int nn = n0 + 8 * j + 2 * tg;
            *(uint32_t*)&d_hbuf[(size_t)(b * Cc + 16 * w + g) * Nn + nn]     = packbf(C[0], C[1]);
            *(uint32_t*)&d_hbuf[(size_t)(b * Cc + 16 * w + g + 8) * Nn + nn] = packbf(C[2], C[3]);
        }
    }
}

// ---------------------------------------------------------------------------
// Kernel 2: warp-mma flash attention over one n-quarter.
//   128 threads (4 warps), warp = 32 m (2 m16 frags), MT=128, NT=64.
// ---------------------------------------------------------------------------
__global__ __launch_bounds__(128) void attn_mma_kernel()
{
    __shared__ float4   fsp[2][4][32];       // permuted f
    __shared__ uint16_t hs[2][Cc][72];       // h [c][n] bf16, stride 72 (144B)

    const int tid  = threadIdx.x;
    const int w    = tid >> 5;
    const int lane = tid & 31;
    const int g    = lane >> 2;
    const int tg   = lane & 3;
    const int b    = blockIdx.y;
    const int m0   = blockIdx.x * MT;
    const int part = blockIdx.z;
    const int nbase = part * NHALF;

    const uint32_t fsb = smem_u32(&fsp[0][0][0]);
    const uint32_t hsb = smem_u32(&hs[0][0][0]);

    uint32_t gfr[2][4];
#pragma unroll
    for (int mf = 0; mf < 2; mf++) {
        const int mb = m0 + w * 32 + mf * 16;
        const float* gp = d_gbuf + (size_t)(b * Nn) * CK;
        gfr[mf][0] = __float_as_uint(gp[(mb + g) * CK + tg]);
        gfr[mf][1] = __float_as_uint(gp[(mb + 8 + g) * CK + tg]);
        gfr[mf][2] = __float_as_uint(gp[(mb + g) * CK + tg + 4]);
        gfr[mf][3] = __float_as_uint(gp[(mb + 8 + g) * CK + tg + 4]);
    }

    float O[2][8][4];
#pragma unroll
    for (int mf = 0; mf < 2; mf++)
#pragma unroll
        for (int cf = 0; cf < 8; cf++)
#pragma unroll
            for (int j = 0; j < 4; j++) O[mf][cf][j] = 0.f;
    float Ls[2][2] = {{0.f, 0.f}, {0.f, 0.f}};

    auto issue_tile = [&](int it) {
        const int p  = it & 1;
        const int n0 = nbase + it * NT;
        {   // f: 4 groups x 32 lanes = 128 cp16
            int t = tid >> 5, l = tid & 31;
            CP16(fsb + (uint32_t)((p * 128 + t * 32 + l) * 16),
                 d_fperm + ((size_t)(b * (Nn / 16) + (n0 >> 4) + t) * 32 + l) * 4);
        }
#pragma unroll
        for (int k = 0; k < 4; k++) {   // h: 64 rows x 8 chunks of 16B
            int e = tid + k * 128;
            int c = e >> 3, ch = e & 7;
            CP16(hsb + (uint32_t)(((p * Cc + c) * 72 + ch * 8) * 2),
                 d_hbuf + (size_t)(b * Cc + c) * Nn + n0 + ch * 8);
        }
    };

    issue_tile(0); CP_COMMIT();
    issue_tile(1); CP_COMMIT();

    const uint32_t lm_row = ((lane >> 4) & 1) * 8 + (lane & 7);
    const uint32_t lm_col = ((lane >> 3) & 1) * 8;

    for (int it = 0; it < NITER; ++it) {
        const int p = it & 1;
        CP_WAIT1();
        __syncthreads();

#pragma unroll
        for (int t = 0; t < NT / 16; t++) {
            float4 fv = fsp[p][t][lane];
            uint32_t fb0 = __float_as_uint(fv.x), fb1 = __float_as_uint(fv.y);
            uint32_t fb2 = __float_as_uint(fv.z), fb3 = __float_as_uint(fv.w);

            float c00[4] = {0, 0, 0, 0}, c01[4] = {0, 0, 0, 0};
            float c10[4] = {0, 0, 0, 0}, c11[4] = {0, 0, 0, 0};
            MMA_TF32(c00, gfr[0][0], gfr[0][1], gfr[0][2], gfr[0][3], fb0, fb1);
            MMA_TF32(c01, gfr[0][0], gfr[0][1], gfr[0][2], gfr[0][3], fb2, fb3);
            MMA_TF32(c10, gfr[1][0], gfr[1][1], gfr[1][2], gfr[1][3], fb0, fb1);
            MMA_TF32(c11, gfr[1][0], gfr[1][1], gfr[1][2], gfr[1][3], fb2, fb3);

            uint32_t pa[2][4];
#pragma unroll
            for (int mf = 0; mf < 2; mf++) {
                float* c0 = mf ? c10 : c00;
                float* c1 = mf ? c11 : c01;
                float p00 = ex2(c0[0]), p01 = ex2(c0[1]), p02 = ex2(c0[2]), p03 = ex2(c0[3]);
                float p10 = ex2(c1[0]), p11 = ex2(c1[1]), p12 = ex2(c1[2]), p13 = ex2(c1[3]);
                Ls[mf][0] += (p00 + p01) + (p10 + p11);
                Ls[mf][1] += (p02 + p03) + (p12 + p13);
                pa[mf][0] = packbf(p00, p01);
                pa[mf][1] = packbf(p02, p03);
                pa[mf][2] = packbf(p10, p11);
                pa[mf][3] = packbf(p12, p13);
            }

#pragma unroll
            for (int p2 = 0; p2 < 4; p2++) {
                uint32_t r0, r1, r2, r3;
                uint32_t addr = hsb + ((p * Cc + 16 * p2 + lm_row) * 72 + 16 * t + lm_col) * 2;
                LDMX4(r0, r1, r2, r3, addr);
                const int cf = 2 * p2;
                MMA_BF16(O[0][cf],     pa[0][0], pa[0][1], pa[0][2], pa[0][3], r0, r1);
                MMA_BF16(O[1][cf],     pa[1][0], pa[1][1], pa[1][2], pa[1][3], r0, r1);
                MMA_BF16(O[0][cf + 1], pa[0][0], pa[0][1], pa[0][2], pa[0][3], r2, r3);
                MMA_BF16(O[1][cf + 1], pa[1][0], pa[1][1], pa[1][2], pa[1][3], r2, r3);
            }
        }
        __syncthreads();
        if (it + 2 < NITER) issue_tile(it + 2);
        CP_COMMIT();
    }

    // quad-reduce row sums
#pragma unroll
    for (int mf = 0; mf < 2; mf++)
#pragma unroll
        for (int hh = 0; hh < 2; hh++) {
            float v = Ls[mf][hh];
            v += __shfl_xor_sync(0xffffffffu, v, 1);
            v += __shfl_xor_sync(0xffffffffu, v, 2);
            Ls[mf][hh] = v;
        }

    // write partials
    const size_t base = (size_t)(part * Bb + b) * Nn;
#pragma unroll
    for (int mf = 0; mf < 2; mf++) {
        const int r = m0 + w * 32 + mf * 16 + g;
#pragma unroll
        for (int cf = 0; cf < 8; cf++) {
            const int c = cf * 8 + 2 * tg;
            *(float2*)&d_Opart[(base + r) * Cc + c]     = make_float2(O[mf][cf][0], O[mf][cf][1]);
            *(float2*)&d_Opart[(base + r + 8) * Cc + c] = make_float2(O[mf][cf][2], O[mf][cf][3]);
        }
        if (tg == 0) {
            d_Lpart[base + r]     = Ls[mf][0];
            d_Lpart[base + r + 8] = Ls[mf][1];
        }
    }
}

// ---------------------------------------------------------------------------
// Kernel 3: combine 4 parts + residual.  out[b][c][m] = ga*sum(O)/sum(L) + x
// ---------------------------------------------------------------------------
__global__ __launch_bounds__(256) void combine_kernel(
    const float* __restrict__ x,
    const float* __restrict__ gamma,
    float* __restrict__ out)
{
    __shared__ float sL[64];
    __shared__ float s[64][65];
    const int b   = blockIdx.y;
    const int m0  = blockIdx.x * 64;
    const int tid = threadIdx.x;
    const float ga = gamma[0];

    if (tid < 64) {
        float L = 0.f;
#pragma unroll
        for (int hh = 0; hh < NSPLIT; hh++)
            L += d_Lpart[(size_t)(hh * Bb + b) * Nn + m0 + tid];
        sL[tid] = ga / L;
    }
    __syncthreads();

#pragma unroll
    for (int k = 0; k < 4; k++) {
        int e = tid + k * 256;
        int ml = e >> 4, cq = e & 15;
        float4 a = make_float4(0.f, 0.f, 0.f, 0.f);
#pragma unroll
        for (int hh = 0; hh < NSPLIT; hh++) {
            const float4 v = *(const float4*)&d_Opart[((size_t)(hh * Bb + b) * Nn + m0 + ml) * Cc + cq * 4];
            a.x += v.x; a.y += v.y; a.z += v.z; a.w += v.w;
        }
        const float inv = sL[ml];
        s[cq * 4 + 0][ml] = a.x * inv;
        s[cq * 4 + 1][ml] = a.y * inv;
        s[cq * 4 + 2][ml] = a.z * inv;
        s[cq * 4 + 3][ml] = a.w * inv;
    }
    __syncthreads();

#pragma unroll
    for (int k = 0; k < 4; k++) {
        int e = tid + k * 256;
        int c = e >> 4, mq = e & 15;
        int gi = (b * Cc + c) * Nn + m0 + mq * 4;
        float4 xv = *(const float4*)&x[gi];
        float4 o;
        o.x = s[c][mq * 4 + 0] + xv.x;
        o.y = s[c][mq * 4 + 1] + xv.y;
        o.z = s[c][mq * 4 + 2] + xv.z;
        o.w = s[c][mq * 4 + 3] + xv.w;
        *(float4*)&out[gi] = o;
    }
}

// ---------------------------------------------------------------------------
extern "C" void kernel_launch(void* const* d_in, const int* in_sizes, int n_in,
                              void* d_out, int out_size)
{
    const float* x     = (const float*)d_in[0];
    const float* wq    = (const float*)d_in[1];
    const float* wk    = (const float*)d_in[2];
    const float* wv    = (const float*)d_in[3];
    const float* gamma = (const float*)d_in[4];
    float* out = (float*)d_out;
    (void)in_sizes; (void)n_in; (void)out_size;

    proj_kernel<<<dim3(Nn / 64, Bb), 128>>>(x, wq, wk, wv);
    attn_mma_kernel<<<dim3(Nn / MT, Bb, NSPLIT), 128>>>();
    combine_kernel<<<dim3(Nn / 64, Bb), 256>>>(x, gamma, out);
}

// round 10
// speedup vs baseline: 1.2730x; 1.0182x over previous
#include <cuda_runtime.h>
#include <cuda_bf16.h>
#include <cstdint>

// SAGAN self-attention, B=8, C=64, N=4096, Ck=8.
// out = gamma * (h @ softmax_n(f^T g)) + x
// All three GEMMs on tensor cores (mma.sync, sm_103 baseline PTX):
//   proj: f/g/h = W x   (tf32 m16n8k8, W in A-frags, cp.async raw loads)
//   attn: gemm1 tf32, gemm2 bf16 with C->A pack, flash over n, NSPLIT=4.
// No max-subtraction (|s|*log2e <= ~25); log2e folded into g output.

#define Bb 8
#define Cc 64
#define Nn 4096
#define CK 8
#define MT 128
#define NT 64
#define NSPLIT 4
#define NHALF (Nn / NSPLIT)
#define NITER (NHALF / NT)
#define LOG2E 1.44269504088896340736f

// Scratch (allocation-free rule: __device__ globals)
__device__ float    d_gbuf[Bb * Nn * CK];             // [b][m][k] tf32 * log2e
__device__ float    d_fperm[Bb * (Nn / 16) * 32 * 4]; // B-frag order per 16-n group
__device__ uint16_t d_hbuf[Bb * Cc * Nn];             // bf16 [b][c][n]
__device__ float    d_Opart[NSPLIT * Bb * Nn * Cc];   // [part][b][m][c]
__device__ float    d_Lpart[NSPLIT * Bb * Nn];        // [part][b][m]

// ---------------- helpers ----------------
__device__ __forceinline__ uint32_t smem_u32(const void* p) {
    uint32_t a;
    asm("{ .reg .u64 t; cvta.to.shared.u64 t, %1; cvt.u32.u64 %0, t; }" : "=r"(a) : "l"(p));
    return a;
}
__device__ __forceinline__ float f2tf(float x) {
    uint32_t r;
    asm("cvt.rna.tf32.f32 %0, %1;" : "=r"(r) : "f"(x));
    return __uint_as_float(r);
}
__device__ __forceinline__ uint32_t f2tfb(float x) {
    uint32_t r;
    asm("cvt.rna.tf32.f32 %0, %1;" : "=r"(r) : "f"(x));
    return r;
}
__device__ __forceinline__ float ex2(float x) {
    float r;
    asm("ex2.approx.f32 %0, %1;" : "=f"(r) : "f"(x));
    return r;
}
__device__ __forceinline__ uint32_t packbf(float lo, float hi) {
    uint32_t d;
    asm("cvt.rn.bf16x2.f32 %0, %1, %2;" : "=r"(d) : "f"(hi), "f"(lo));
    return d;
}

#define MMA_TF32(d, a0, a1, a2, a3, b0, b1)                                   \
    asm volatile("mma.sync.aligned.m16n8k8.row.col.f32.tf32.tf32.f32 "        \
                 "{%0,%1,%2,%3}, {%4,%5,%6,%7}, {%8,%9}, {%0,%1,%2,%3};"      \
                 : "+f"((d)[0]), "+f"((d)[1]), "+f"((d)[2]), "+f"((d)[3])     \
                 : "r"(a0), "r"(a1), "r"(a2), "r"(a3), "r"(b0), "r"(b1))

#define MMA_BF16(d, a0, a1, a2, a3, b0, b1)                                   \
    asm volatile("mma.sync.aligned.m16n8k16.row.col.f32.bf16.bf16.f32 "       \
                 "{%0,%1,%2,%3}, {%4,%5,%6,%7}, {%8,%9}, {%0,%1,%2,%3};"      \
                 : "+f"((d)[0]), "+f"((d)[1]), "+f"((d)[2]), "+f"((d)[3])     \
                 : "r"(a0), "r"(a1), "r"(a2), "r"(a3), "r"(b0), "r"(b1))

#define LDMX4(r0, r1, r2, r3, addr)                                           \
    asm volatile("ldmatrix.sync.aligned.m8n8.x4.shared.b16 {%0,%1,%2,%3}, [%4];" \
                 : "=r"(r0), "=r"(r1), "=r"(r2), "=r"(r3) : "r"(addr))

#define CP16(dst, src) \
    asm volatile("cp.async.cg.shared.global [%0], [%1], 16;" :: "r"(dst), "l"(src))
#define CP_COMMIT()  asm volatile("cp.async.commit_group;" ::: "memory")
#define CP_WAIT1()   asm volatile("cp.async.wait_group 1;" ::: "memory")
#define CP_WAITALL() asm volatile("cp.async.wait_all;" ::: "memory")

// ---------------------------------------------------------------------------
// Kernel 1: projections via tf32 mma, cp.async raw loads, convert-on-read.
//   Block = 64 pixels, 256 threads (8 warps).
//   f/g: warp w -> px group 8w (one n8 MMA col group), rows 0-7 f, 8-15 g.
//   h:   warp w -> wv row group 16*(w&3), px half 32*(w>>2).
// ---------------------------------------------------------------------------
__global__ __launch_bounds__(256) void proj_kernel(
    const float* __restrict__ x,
    const float* __restrict__ wq,
    const float* __restrict__ wk,
    const float* __restrict__ wv)
{
    __shared__ float wqk_s[16][68];   // raw: rows 0-7 wq, 8-15 wk
    __shared__ float wv_s[64][68];    // raw wv
    __shared__ float xs[64][72];      // raw x tile [ch][px]
    __shared__ float f_st[8][68];     // f staging [row][px] (tf32)
    __shared__ float g_st[64][8];     // g staging [px][row] (tf32 * log2e)

    const int b    = blockIdx.y;
    const int n0   = blockIdx.x * 64;
    const int tid  = threadIdx.x;
    const int w    = tid >> 5;
    const int lane = tid & 31;
    const int g    = lane >> 2;   // 0..7
    const int tg   = lane & 3;    // 0..3

    const uint32_t wqk_b = smem_u32(&wqk_s[0][0]);
    const uint32_t wv_b  = smem_u32(&wv_s[0][0]);
    const uint32_t xs_b  = smem_u32(&xs[0][0]);

    // cp.async raw loads: wqk 256 cp16, wv 1024 cp16, xs 1024 cp16
    {
        int r = tid >> 4, c4 = (tid & 15) * 4;   // 256 threads cover 16x16
        const float* src = (r < 8) ? (wq + r * Cc + c4) : (wk + (r - 8) * Cc + c4);
        CP16(wqk_b + (uint32_t)((r * 68 + c4) * 4), src);
    }
#pragma unroll
    for (int k = 0; k < 4; k++) {
        int e = tid + k * 256;
        int r = e >> 4, c4 = (e & 15) * 4;
        CP16(wv_b + (uint32_t)((r * 68 + c4) * 4), wv + r * Cc + c4);
    }
#pragma unroll
    for (int k = 0; k < 4; k++) {
        int e = tid + k * 256;
        int ch = e >> 4, q4 = (e & 15) * 4;
        CP16(xs_b + (uint32_t)((ch * 72 + q4) * 4),
             x + (size_t)(b * Cc + ch) * Nn + n0 + q4);
    }
    CP_WAITALL();
    __syncthreads();

    // ---- f/g: warp w covers px group 8w ----
    {
        const int px0 = 8 * w;
        float C[4] = {0.f, 0.f, 0.f, 0.f};
#pragma unroll
        for (int ks = 0; ks < 8; ks++) {
            uint32_t a0 = f2tfb(wqk_s[g][8 * ks + tg]);
            uint32_t a1 = f2tfb(wqk_s[g + 8][8 * ks + tg]);
            uint32_t a2 = f2tfb(wqk_s[g][8 * ks + tg + 4]);
            uint32_t a3 = f2tfb(wqk_s[g + 8][8 * ks + tg + 4]);
            uint32_t b0 = f2tfb(xs[8 * ks + tg][px0 + g]);
            uint32_t b1 = f2tfb(xs[8 * ks + tg + 4][px0 + g]);
            MMA_TF32(C, a0, a1, a2, a3, b0, b1);
        }
        f_st[g][px0 + 2 * tg]     = f2tf(C[0]);
        f_st[g][px0 + 2 * tg + 1] = f2tf(C[1]);
        g_st[px0 + 2 * tg][g]     = f2tf(C[2] * LOG2E);
        g_st[px0 + 2 * tg + 1][g] = f2tf(C[3] * LOG2E);
    }

    // ---- h: warp w -> wv rows 16*(w&3).., px half 32*(w>>2) ----
    {
        const int a4 = (w & 3) * 16;
        const int jb = (w >> 2) * 4;
        uint32_t av[8][4];
#pragma unroll
        for (int ks = 0; ks < 8; ks++) {
            av[ks][0] = f2tfb(wv_s[a4 + g][8 * ks + tg]);
            av[ks][1] = f2tfb(wv_s[a4 + g + 8][8 * ks + tg]);
            av[ks][2] = f2tfb(wv_s[a4 + g][8 * ks + tg + 4]);
            av[ks][3] = f2tfb(wv_s[a4 + g + 8][8 * ks + tg + 4]);
        }
#pragma unroll
        for (int j = jb; j < jb + 4; j++) {
            float C[4] = {0.f, 0.f, 0.f, 0.f};
#pragma unroll
            for (int ks = 0; ks < 8; ks++) {
                uint32_t b0 = f2tfb(xs[8 * ks + tg][8 * j + g]);
                uint32_t b1 = f2tfb(xs[8 * ks + tg + 4][8 * j + g]);
                MMA_TF32(C, av[ks][0], av[ks][1], av[ks][2], av[ks][3], b0, b1);
            }
            const int nn = n0 + 8 * j + 2 * tg;
            *(uint32_t*)&d_hbuf[(size_t)(b * Cc + a4 + g) * Nn + nn]     = packbf(C[0], C[1]);
            *(uint32_t*)&d_hbuf[(size_t)(b * Cc + a4 + g + 8) * Nn + nn] = packbf(C[2], C[3]);
        }
    }
    __syncthreads();

    // ---- writeouts from staging (threads 0..127) ----
    if (tid < 128) {
        {   // d_fperm: group t = tid>>5 (16 px), B-frag float4 per lane
            int t = tid >> 5, l = tid & 31, gg = l >> 2, tt = l & 3;
            float4 v = make_float4(f_st[tt][16 * t + gg],     f_st[tt + 4][16 * t + gg],
                                   f_st[tt][16 * t + 8 + gg], f_st[tt + 4][16 * t + 8 + gg]);
            ((float4*)d_fperm)[(size_t)(b * (Nn / 16) + (n0 >> 4) + t) * 32 + l] = v;
        }
        {   // d_gbuf: [m][k], 64 px x 2 float4
            int px = tid >> 1, hf = tid & 1;
            float4 gv = *(float4*)&g_st[px][4 * hf];
            *(float4*)&d_gbuf[(size_t)(b * Nn + n0 + px) * CK + 4 * hf] = gv;
        }
    }
}

// ---------------------------------------------------------------------------
// Kernel 2: warp-mma flash attention over one n-quarter.
//   128 threads (4 warps), warp = 32 m (2 m16 frags), MT=128, NT=64.
// ---------------------------------------------------------------------------
__global__ __launch_bounds__(128) void attn_mma_kernel()
{
    __shared__ float4   fsp[2][4][32];       // permuted f
    __shared__ uint16_t hs[2][Cc][72];       // h [c][n] bf16, stride 72 (144B)

    const int tid  = threadIdx.x;
    const int w    = tid >> 5;
    const int lane = tid & 31;
    const int g    = lane >> 2;
    const int tg   = lane & 3;
    const int b    = blockIdx.y;
    const int m0   = blockIdx.x * MT;
    const int part = blockIdx.z;
    const int nbase = part * NHALF;

    const uint32_t fsb = smem_u32(&fsp[0][0][0]);
    const uint32_t hsb = smem_u32(&hs[0][0][0]);

    uint32_t gfr[2][4];
#pragma unroll
    for (int mf = 0; mf < 2; mf++) {
        const int mb = m0 + w * 32 + mf * 16;
        const float* gp = d_gbuf + (size_t)(b * Nn) * CK;
        gfr[mf][0] = __float_as_uint(gp[(mb + g) * CK + tg]);
        gfr[mf][1] = __float_as_uint(gp[(mb + 8 + g) * CK + tg]);
        gfr[mf][2] = __float_as_uint(gp[(mb + g) * CK + tg + 4]);
        gfr[mf][3] = __float_as_uint(gp[(mb + 8 + g) * CK + tg + 4]);
    }

    float O[2][8][4];
#pragma unroll
    for (int mf = 0; mf < 2; mf++)
#pragma unroll
        for (int cf = 0; cf < 8; cf++)
#pragma unroll
            for (int j = 0; j < 4; j++) O[mf][cf][j] = 0.f;
    float Ls[2][2] = {{0.f, 0.f}, {0.f, 0.f}};

    auto issue_tile = [&](int it) {
        const int p  = it & 1;
        const int n0 = nbase + it * NT;
        {   // f: 4 groups x 32 lanes = 128 cp16
            int t = tid >> 5, l = tid & 31;
            CP16(fsb + (uint32_t)((p * 128 + t * 32 + l) * 16),
                 d_fperm + ((size_t)(b * (Nn / 16) + (n0 >> 4) + t) * 32 + l) * 4);
        }
#pragma unroll
        for (int k = 0; k < 4; k++) {   // h: 64 rows x 8 chunks of 16B
            int e = tid + k * 128;
            int c = e >> 3, ch = e & 7;
            CP16(hsb + (uint32_t)(((p * Cc + c) * 72 + ch * 8) * 2),
                 d_hbuf + (size_t)(b * Cc + c) * Nn + n0 + ch * 8);
        }
    };

    issue_tile(0); CP_COMMIT();
    issue_tile(1); CP_COMMIT();

    const uint32_t lm_row = ((lane >> 4) & 1) * 8 + (lane & 7);
    const uint32_t lm_col = ((lane >> 3) & 1) * 8;

    for (int it = 0; it < NITER; ++it) {
        const int p = it & 1;
        CP_WAIT1();
        __syncthreads();

#pragma unroll
        for (int t = 0; t < NT / 16; t++) {
            float4 fv = fsp[p][t][lane];
            uint32_t fb0 = __float_as_uint(fv.x), fb1 = __float_as_uint(fv.y);
            uint32_t fb2 = __float_as_uint(fv.z), fb3 = __float_as_uint(fv.w);

            float c00[4] = {0, 0, 0, 0}, c01[4] = {0, 0, 0, 0};
            float c10[4] = {0, 0, 0, 0}, c11[4] = {0, 0, 0, 0};
            MMA_TF32(c00, gfr[0][0], gfr[0][1], gfr[0][2], gfr[0][3], fb0, fb1);
            MMA_TF32(c01, gfr[0][0], gfr[0][1], gfr[0][2], gfr[0][3], fb2, fb3);
            MMA_TF32(c10, gfr[1][0], gfr[1][1], gfr[1][2], gfr[1][3], fb0, fb1);
            MMA_TF32(c11, gfr[1][0], gfr[1][1], gfr[1][2], gfr[1][3], fb2, fb3);

            uint32_t pa[2][4];
#pragma unroll
            for (int mf = 0; mf < 2; mf++) {
                float* c0 = mf ? c10 : c00;
                float* c1 = mf ? c11 : c01;
                float p00 = ex2(c0[0]), p01 = ex2(c0[1]), p02 = ex2(c0[2]), p03 = ex2(c0[3]);
                float p10 = ex2(c1[0]), p11 = ex2(c1[1]), p12 = ex2(c1[2]), p13 = ex2(c1[3]);
                Ls[mf][0] += (p00 + p01) + (p10 + p11);
                Ls[mf][1] += (p02 + p03) + (p12 + p13);
                pa[mf][0] = packbf(p00, p01);
                pa[mf][1] = packbf(p02, p03);
                pa[mf][2] = packbf(p10, p11);
                pa[mf][3] = packbf(p12, p13);
            }

#pragma unroll
            for (int p2 = 0; p2 < 4; p2++) {
                uint32_t r0, r1, r2, r3;
                uint32_t addr = hsb + ((p * Cc + 16 * p2 + lm_row) * 72 + 16 * t + lm_col) * 2;
                LDMX4(r0, r1, r2, r3, addr);
                const int cf = 2 * p2;
                MMA_BF16(O[0][cf],     pa[0][0], pa[0][1], pa[0][2], pa[0][3], r0, r1);
                MMA_BF16(O[1][cf],     pa[1][0], pa[1][1], pa[1][2], pa[1][3], r0, r1);
                MMA_BF16(O[0][cf + 1], pa[0][0], pa[0][1], pa[0][2], pa[0][3], r2, r3);
                MMA_BF16(O[1][cf + 1], pa[1][0], pa[1][1], pa[1][2], pa[1][3], r2, r3);
            }
        }
        __syncthreads();
        if (it + 2 < NITER) issue_tile(it + 2);
        CP_COMMIT();
    }

    // quad-reduce row sums
#pragma unroll
    for (int mf = 0; mf < 2; mf++)
#pragma unroll
        for (int hh = 0; hh < 2; hh++) {
            float v = Ls[mf][hh];
            v += __shfl_xor_sync(0xffffffffu, v, 1);
            v += __shfl_xor_sync(0xffffffffu, v, 2);
            Ls[mf][hh] = v;
        }

    // write partials
    const size_t base = (size_t)(part * Bb + b) * Nn;
#pragma unroll
    for (int mf = 0; mf < 2; mf++) {
        const int r = m0 + w * 32 + mf * 16 + g;
#pragma unroll
        for (int cf = 0; cf < 8; cf++) {
            const int c = cf * 8 + 2 * tg;
            *(float2*)&d_Opart[(base + r) * Cc + c]     = make_float2(O[mf][cf][0], O[mf][cf][1]);
            *(float2*)&d_Opart[(base + r + 8) * Cc + c] = make_float2(O[mf][cf][2], O[mf][cf][3]);
        }
        if (tg == 0) {
            d_Lpart[base + r]     = Ls[mf][0];
            d_Lpart[base + r + 8] = Ls[mf][1];
        }
    }
}

// ---------------------------------------------------------------------------
// Kernel 3: combine 4 parts + residual.  out[b][c][m] = ga*sum(O)/sum(L) + x
// ---------------------------------------------------------------------------
__global__ __launch_bounds__(256) void combine_kernel(
    const float* __restrict__ x,
    const float* __restrict__ gamma,
    float* __restrict__ out)
{
    __shared__ float sL[64];
    __shared__ float s[64][65];
    const int b   = blockIdx.y;
    const int m0  = blockIdx.x * 64;
    const int tid = threadIdx.x;
    const float ga = gamma[0];

    if (tid < 64) {
        float L = 0.f;
#pragma unroll
        for (int hh = 0; hh < NSPLIT; hh++)
            L += d_Lpart[(size_t)(hh * Bb + b) * Nn + m0 + tid];
        sL[tid] = ga / L;
    }
    __syncthreads();

#pragma unroll
    for (int k = 0; k < 4; k++) {
        int e = tid + k * 256;
        int ml = e >> 4, cq = e & 15;
        float4 a = make_float4(0.f, 0.f, 0.f, 0.f);
#pragma unroll
        for (int hh = 0; hh < NSPLIT; hh++) {
            const float4 v = *(const float4*)&d_Opart[((size_t)(hh * Bb + b) * Nn + m0 + ml) * Cc + cq * 4];
            a.x += v.x; a.y += v.y; a.z += v.z; a.w += v.w;
        }
        const float inv = sL[ml];
        s[cq * 4 + 0][ml] = a.x * inv;
        s[cq * 4 + 1][ml] = a.y * inv;
        s[cq * 4 + 2][ml] = a.z * inv;
        s[cq * 4 + 3][ml] = a.w * inv;
    }
    __syncthreads();

#pragma unroll
    for (int k = 0; k < 4; k++) {
        int e = tid + k * 256;
        int c = e >> 4, mq = e & 15;
        int gi = (b * Cc + c) * Nn + m0 + mq * 4;
        float4 xv = *(const float4*)&x[gi];
        float4 o;
        o.x = s[c][mq * 4 + 0] + xv.x;
        o.y = s[c][mq * 4 + 1] + xv.y;
        o.z = s[c][mq * 4 + 2] + xv.z;
        o.w = s[c][mq * 4 + 3] + xv.w;
        *(float4*)&out[gi] = o;
    }
}

// ---------------------------------------------------------------------------
extern "C" void kernel_launch(void* const* d_in, const int* in_sizes, int n_in,
                              void* d_out, int out_size)
{
    const float* x     = (const float*)d_in[0];
    const float* wq    = (const float*)d_in[1];
    const float* wk    = (const float*)d_in[2];
    const float* wv    = (const float*)d_in[3];
    const float* gamma = (const float*)d_in[4];
    float* out = (float*)d_out;
    (void)in_sizes; (void)n_in; (void)out_size;

    proj_kernel<<<dim3(Nn / 64, Bb), 256>>>(x, wq, wk, wv);
    attn_mma_kernel<<<dim3(Nn / MT, Bb, NSPLIT), 128>>>();
    combine_kernel<<<dim3(Nn / 64, Bb), 256>>>(x, gamma, out);
}

// round 11
// speedup vs baseline: 1.3384x; 1.0513x over previous
#include <cuda_runtime.h>
#include <cuda_bf16.h>
#include <cstdint>

// SAGAN self-attention, B=8, C=64, N=4096, Ck=8.
// out = gamma * (h @ softmax_n(f^T g)) + x
// All three GEMMs on tensor cores (mma.sync, sm_103 baseline PTX):
//   proj: f/g/h = W x   (tf32 m16n8k8, W in A-frags, cp.async split-group loads)
//   attn: gemm1 tf32, gemm2 bf16 with C->A pack, flash over n, NSPLIT=4, NT=128.
// No max-subtraction (|s|*log2e <= ~25); log2e folded into g output.

#define Bb 8
#define Cc 64
#define Nn 4096
#define CK 8
#define MT 128
#define NT 128
#define NSPLIT 4
#define NHALF (Nn / NSPLIT)
#define NITER (NHALF / NT)
#define LOG2E 1.44269504088896340736f

// Scratch (allocation-free rule: __device__ globals)
__device__ float    d_gbuf[Bb * Nn * CK];             // [b][m][k] tf32 * log2e
__device__ float    d_fperm[Bb * (Nn / 16) * 32 * 4]; // B-frag order per 16-n group
__device__ uint16_t d_hbuf[Bb * Cc * Nn];             // bf16 [b][c][n]
__device__ float    d_Opart[NSPLIT * Bb * Nn * Cc];   // [part][b][m][c]
__device__ float    d_Lpart[NSPLIT * Bb * Nn];        // [part][b][m]

// ---------------- helpers ----------------
__device__ __forceinline__ uint32_t smem_u32(const void* p) {
    uint32_t a;
    asm("{ .reg .u64 t; cvta.to.shared.u64 t, %1; cvt.u32.u64 %0, t; }" : "=r"(a) : "l"(p));
    return a;
}
__device__ __forceinline__ float f2tf(float x) {
    uint32_t r;
    asm("cvt.rna.tf32.f32 %0, %1;" : "=r"(r) : "f"(x));
    return __uint_as_float(r);
}
__device__ __forceinline__ uint32_t f2tfb(float x) {
    uint32_t r;
    asm("cvt.rna.tf32.f32 %0, %1;" : "=r"(r) : "f"(x));
    return r;
}
__device__ __forceinline__ float ex2(float x) {
    float r;
    asm("ex2.approx.f32 %0, %1;" : "=f"(r) : "f"(x));
    return r;
}
__device__ __forceinline__ uint32_t packbf(float lo, float hi) {
    uint32_t d;
    asm("cvt.rn.bf16x2.f32 %0, %1, %2;" : "=r"(d) : "f"(hi), "f"(lo));
    return d;
}

#define MMA_TF32(d, a0, a1, a2, a3, b0, b1)                                   \
    asm volatile("mma.sync.aligned.m16n8k8.row.col.f32.tf32.tf32.f32 "        \
                 "{%0,%1,%2,%3}, {%4,%5,%6,%7}, {%8,%9}, {%0,%1,%2,%3};"      \
                 : "+f"((d)[0]), "+f"((d)[1]), "+f"((d)[2]), "+f"((d)[3])     \
                 : "r"(a0), "r"(a1), "r"(a2), "r"(a3), "r"(b0), "r"(b1))

#define MMA_BF16(d, a0, a1, a2, a3, b0, b1)                                   \
    asm volatile("mma.sync.aligned.m16n8k16.row.col.f32.bf16.bf16.f32 "       \
                 "{%0,%1,%2,%3}, {%4,%5,%6,%7}, {%8,%9}, {%0,%1,%2,%3};"      \
                 : "+f"((d)[0]), "+f"((d)[1]), "+f"((d)[2]), "+f"((d)[3])     \
                 : "r"(a0), "r"(a1), "r"(a2), "r"(a3), "r"(b0), "r"(b1))

#define LDMX4(r0, r1, r2, r3, addr)                                           \
    asm volatile("ldmatrix.sync.aligned.m8n8.x4.shared.b16 {%0,%1,%2,%3}, [%4];" \
                 : "=r"(r0), "=r"(r1), "=r"(r2), "=r"(r3) : "r"(addr))

#define CP16(dst, src) \
    asm volatile("cp.async.cg.shared.global [%0], [%1], 16;" :: "r"(dst), "l"(src))
#define CP_COMMIT()  asm volatile("cp.async.commit_group;" ::: "memory")
#define CP_WAIT1()   asm volatile("cp.async.wait_group 1;" ::: "memory")
#define CP_WAITALL() asm volatile("cp.async.wait_all;" ::: "memory")

// ---------------------------------------------------------------------------
// Kernel 1: projections via tf32 mma, cp.async split-group loads.
//   Block = 64 pixels, 256 threads (8 warps).
//   Group A = wqk + x (f/g compute starts while group B = wv still loads).
// ---------------------------------------------------------------------------
__global__ __launch_bounds__(256) void proj_kernel(
    const float* __restrict__ x,
    const float* __restrict__ wq,
    const float* __restrict__ wk,
    const float* __restrict__ wv)
{
    __shared__ float wqk_s[16][68];   // raw: rows 0-7 wq, 8-15 wk
    __shared__ float wv_s[64][68];    // raw wv
    __shared__ float xs[64][72];      // raw x tile [ch][px]
    __shared__ float f_st[8][68];     // f staging [row][px] (tf32)
    __shared__ float g_st[64][8];     // g staging [px][row] (tf32 * log2e)

    const int b    = blockIdx.y;
    const int n0   = blockIdx.x * 64;
    const int tid  = threadIdx.x;
    const int w    = tid >> 5;
    const int lane = tid & 31;
    const int g    = lane >> 2;   // 0..7
    const int tg   = lane & 3;    // 0..3

    const uint32_t wqk_b = smem_u32(&wqk_s[0][0]);
    const uint32_t wv_b  = smem_u32(&wv_s[0][0]);
    const uint32_t xs_b  = smem_u32(&xs[0][0]);

    // Group A: wqk (256 cp16) + x (1024 cp16)
    {
        int r = tid >> 4, c4 = (tid & 15) * 4;
        const float* src = (r < 8) ? (wq + r * Cc + c4) : (wk + (r - 8) * Cc + c4);
        CP16(wqk_b + (uint32_t)((r * 68 + c4) * 4), src);
    }
#pragma unroll
    for (int k = 0; k < 4; k++) {
        int e = tid + k * 256;
        int ch = e >> 4, q4 = (e & 15) * 4;
        CP16(xs_b + (uint32_t)((ch * 72 + q4) * 4),
             x + (size_t)(b * Cc + ch) * Nn + n0 + q4);
    }
    CP_COMMIT();
    // Group B: wv (1024 cp16)
#pragma unroll
    for (int k = 0; k < 4; k++) {
        int e = tid + k * 256;
        int r = e >> 4, c4 = (e & 15) * 4;
        CP16(wv_b + (uint32_t)((r * 68 + c4) * 4), wv + r * Cc + c4);
    }
    CP_COMMIT();

    CP_WAIT1();            // group A landed (B may still be in flight)
    __syncthreads();

    // ---- f/g: warp w covers px group 8w ----
    {
        const int px0 = 8 * w;
        float C[4] = {0.f, 0.f, 0.f, 0.f};
#pragma unroll
        for (int ks = 0; ks < 8; ks++) {
            uint32_t a0 = f2tfb(wqk_s[g][8 * ks + tg]);
            uint32_t a1 = f2tfb(wqk_s[g + 8][8 * ks + tg]);
            uint32_t a2 = f2tfb(wqk_s[g][8 * ks + tg + 4]);
            uint32_t a3 = f2tfb(wqk_s[g + 8][8 * ks + tg + 4]);
            uint32_t b0 = f2tfb(xs[8 * ks + tg][px0 + g]);
            uint32_t b1 = f2tfb(xs[8 * ks + tg + 4][px0 + g]);
            MMA_TF32(C, a0, a1, a2, a3, b0, b1);
        }
        f_st[g][px0 + 2 * tg]     = f2tf(C[0]);
        f_st[g][px0 + 2 * tg + 1] = f2tf(C[1]);
        g_st[px0 + 2 * tg][g]     = f2tf(C[2] * LOG2E);
        g_st[px0 + 2 * tg + 1][g] = f2tf(C[3] * LOG2E);
    }

    CP_WAITALL();          // wv landed
    __syncthreads();

    // ---- h: warp w -> wv rows 16*(w&3).., px half 32*(w>>2) ----
    {
        const int a4 = (w & 3) * 16;
        const int jb = (w >> 2) * 4;
        uint32_t av[8][4];
#pragma unroll
        for (int ks = 0; ks < 8; ks++) {
            av[ks][0] = f2tfb(wv_s[a4 + g][8 * ks + tg]);
            av[ks][1] = f2tfb(wv_s[a4 + g + 8][8 * ks + tg]);
            av[ks][2] = f2tfb(wv_s[a4 + g][8 * ks + tg + 4]);
            av[ks][3] = f2tfb(wv_s[a4 + g + 8][8 * ks + tg + 4]);
        }
#pragma unroll
        for (int j = jb; j < jb + 4; j++) {
            float C[4] = {0.f, 0.f, 0.f, 0.f};
#pragma unroll
            for (int ks = 0; ks < 8; ks++) {
                uint32_t b0 = f2tfb(xs[8 * ks + tg][8 * j + g]);
                uint32_t b1 = f2tfb(xs[8 * ks + tg + 4][8 * j + g]);
                MMA_TF32(C, av[ks][0], av[ks][1], av[ks][2], av[ks][3], b0, b1);
            }
            const int nn = n0 + 8 * j + 2 * tg;
            *(uint32_t*)&d_hbuf[(size_t)(b * Cc + a4 + g) * Nn + nn]     = packbf(C[0], C[1]);
            *(uint32_t*)&d_hbuf[(size_t)(b * Cc + a4 + g + 8) * Nn + nn] = packbf(C[2], C[3]);
        }
    }

    // ---- writeouts from staging (threads 0..127; f/g staged before 2nd sync) ----
    if (tid < 128) {
        {
            int t = tid >> 5, l = tid & 31, gg = l >> 2, tt = l & 3;
            float4 v = make_float4(f_st[tt][16 * t + gg],     f_st[tt + 4][16 * t + gg],
                                   f_st[tt][16 * t + 8 + gg], f_st[tt + 4][16 * t + 8 + gg]);
            ((float4*)d_fperm)[(size_t)(b * (Nn / 16) + (n0 >> 4) + t) * 32 + l] = v;
        }
        {
            int px = tid >> 1, hf = tid & 1;
            float4 gv = *(float4*)&g_st[px][4 * hf];
            *(float4*)&d_gbuf[(size_t)(b * Nn + n0 + px) * CK + 4 * hf] = gv;
        }
    }
}

// ---------------------------------------------------------------------------
// Kernel 2: warp-mma flash attention over one n-quarter.
//   128 threads (4 warps), warp = 32 m (2 m16 frags), MT=128, NT=128.
// ---------------------------------------------------------------------------
__global__ __launch_bounds__(128) void attn_mma_kernel()
{
    __shared__ float4   fsp[2][8][32];       // permuted f
    __shared__ uint16_t hs[2][Cc][136];      // h [c][n] bf16, stride 136 (272B)

    const int tid  = threadIdx.x;
    const int w    = tid >> 5;
    const int lane = tid & 31;
    const int g    = lane >> 2;
    const int tg   = lane & 3;
    const int b    = blockIdx.y;
    const int m0   = blockIdx.x * MT;
    const int part = blockIdx.z;
    const int nbase = part * NHALF;

    const uint32_t fsb = smem_u32(&fsp[0][0][0]);
    const uint32_t hsb = smem_u32(&hs[0][0][0]);

    uint32_t gfr[2][4];
#pragma unroll
    for (int mf = 0; mf < 2; mf++) {
        const int mb = m0 + w * 32 + mf * 16;
        const float* gp = d_gbuf + (size_t)(b * Nn) * CK;
        gfr[mf][0] = __float_as_uint(gp[(mb + g) * CK + tg]);
        gfr[mf][1] = __float_as_uint(gp[(mb + 8 + g) * CK + tg]);
        gfr[mf][2] = __float_as_uint(gp[(mb + g) * CK + tg + 4]);
        gfr[mf][3] = __float_as_uint(gp[(mb + 8 + g) * CK + tg + 4]);
    }

    float O[2][8][4];
#pragma unroll
    for (int mf = 0; mf < 2; mf++)
#pragma unroll
        for (int cf = 0; cf < 8; cf++)
#pragma unroll
            for (int j = 0; j < 4; j++) O[mf][cf][j] = 0.f;
    float Ls[2][2] = {{0.f, 0.f}, {0.f, 0.f}};

    auto issue_tile = [&](int it) {
        const int p  = it & 1;
        const int n0 = nbase + it * NT;
#pragma unroll
        for (int k = 0; k < 2; k++) {   // f: 8 groups x 32 lanes = 256 cp16
            int e = tid + k * 128;
            int t = e >> 5, l = e & 31;
            CP16(fsb + (uint32_t)((p * 256 + t * 32 + l) * 16),
                 d_fperm + ((size_t)(b * (Nn / 16) + (n0 >> 4) + t) * 32 + l) * 4);
        }
#pragma unroll
        for (int k = 0; k < 8; k++) {   // h: 64 rows x 16 chunks of 16B
            int e = tid + k * 128;
            int c = e >> 4, ch = e & 15;
            CP16(hsb + (uint32_t)(((p * Cc + c) * 136 + ch * 8) * 2),
                 d_hbuf + (size_t)(b * Cc + c) * Nn + n0 + ch * 8);
        }
    };

    issue_tile(0); CP_COMMIT();
    issue_tile(1); CP_COMMIT();

    const uint32_t lm_row = ((lane >> 4) & 1) * 8 + (lane & 7);
    const uint32_t lm_col = ((lane >> 3) & 1) * 8;

    for (int it = 0; it < NITER; ++it) {
        const int p = it & 1;
        CP_WAIT1();
        __syncthreads();

#pragma unroll
        for (int t = 0; t < NT / 16; t++) {
            float4 fv = fsp[p][t][lane];
            uint32_t fb0 = __float_as_uint(fv.x), fb1 = __float_as_uint(fv.y);
            uint32_t fb2 = __float_as_uint(fv.z), fb3 = __float_as_uint(fv.w);

            float c00[4] = {0, 0, 0, 0}, c01[4] = {0, 0, 0, 0};
            float c10[4] = {0, 0, 0, 0}, c11[4] = {0, 0, 0, 0};
            MMA_TF32(c00, gfr[0][0], gfr[0][1], gfr[0][2], gfr[0][3], fb0, fb1);
            MMA_TF32(c01, gfr[0][0], gfr[0][1], gfr[0][2], gfr[0][3], fb2, fb3);
            MMA_TF32(c10, gfr[1][0], gfr[1][1], gfr[1][2], gfr[1][3], fb0, fb1);
            MMA_TF32(c11, gfr[1][0], gfr[1][1], gfr[1][2], gfr[1][3], fb2, fb3);

            uint32_t pa[2][4];
#pragma unroll
            for (int mf = 0; mf < 2; mf++) {
                float* c0 = mf ? c10 : c00;
                float* c1 = mf ? c11 : c01;
                float p00 = ex2(c0[0]), p01 = ex2(c0[1]), p02 = ex2(c0[2]), p03 = ex2(c0[3]);
                float p10 = ex2(c1[0]), p11 = ex2(c1[1]), p12 = ex2(c1[2]), p13 = ex2(c1[3]);
                Ls[mf][0] += (p00 + p01) + (p10 + p11);
                Ls[mf][1] += (p02 + p03) + (p12 + p13);
                pa[mf][0] = packbf(p00, p01);
                pa[mf][1] = packbf(p02, p03);
                pa[mf][2] = packbf(p10, p11);
                pa[mf][3] = packbf(p12, p13);
            }

#pragma unroll
            for (int p2 = 0; p2 < 4; p2++) {
                uint32_t r0, r1, r2, r3;
                uint32_t addr = hsb + ((p * Cc + 16 * p2 + lm_row) * 136 + 16 * t + lm_col) * 2;
                LDMX4(r0, r1, r2, r3, addr);
                const int cf = 2 * p2;
                MMA_BF16(O[0][cf],     pa[0][0], pa[0][1], pa[0][2], pa[0][3], r0, r1);
                MMA_BF16(O[1][cf],     pa[1][0], pa[1][1], pa[1][2], pa[1][3], r0, r1);
                MMA_BF16(O[0][cf + 1], pa[0][0], pa[0][1], pa[0][2], pa[0][3], r2, r3);
                MMA_BF16(O[1][cf + 1], pa[1][0], pa[1][1], pa[1][2], pa[1][3], r2, r3);
            }
        }
        __syncthreads();
        if (it + 2 < NITER) issue_tile(it + 2);
        CP_COMMIT();
    }

    // quad-reduce row sums
#pragma unroll
    for (int mf = 0; mf < 2; mf++)
#pragma unroll
        for (int hh = 0; hh < 2; hh++) {
            float v = Ls[mf][hh];
            v += __shfl_xor_sync(0xffffffffu, v, 1);
            v += __shfl_xor_sync(0xffffffffu, v, 2);
            Ls[mf][hh] = v;
        }

    // write partials
    const size_t base = (size_t)(part * Bb + b) * Nn;
#pragma unroll
    for (int mf = 0; mf < 2; mf++) {
        const int r = m0 + w * 32 + mf * 16 + g;
#pragma unroll
        for (int cf = 0; cf < 8; cf++) {
            const int c = cf * 8 + 2 * tg;
            *(float2*)&d_Opart[(base + r) * Cc + c]     = make_float2(O[mf][cf][0], O[mf][cf][1]);
            *(float2*)&d_Opart[(base + r + 8) * Cc + c] = make_float2(O[mf][cf][2], O[mf][cf][3]);
        }
        if (tg == 0) {
            d_Lpart[base + r]     = Ls[mf][0];
            d_Lpart[base + r + 8] = Ls[mf][1];
        }
    }
}

// ---------------------------------------------------------------------------
// Kernel 3: combine 4 parts + residual.  out[b][c][m] = ga*sum(O)/sum(L) + x
// ---------------------------------------------------------------------------
__global__ __launch_bounds__(256) void combine_kernel(
    const float* __restrict__ x,
    const float* __restrict__ gamma,
    float* __restrict__ out)
{
    __shared__ float sL[64];
    __shared__ float s[64][65];
    const int b   = blockIdx.y;
    const int m0  = blockIdx.x * 64;
    const int tid = threadIdx.x;
    const float ga = gamma[0];

    if (tid < 64) {
        float L = 0.f;
#pragma unroll
        for (int hh = 0; hh < NSPLIT; hh++)
            L += d_Lpart[(size_t)(hh * Bb + b) * Nn + m0 + tid];
        sL[tid] = ga / L;
    }
    __syncthreads();

#pragma unroll
    for (int k = 0; k < 4; k++) {
        int e = tid + k * 256;
        int ml = e >> 4, cq = e & 15;
        float4 a = make_float4(0.f, 0.f, 0.f, 0.f);
#pragma unroll
        for (int hh = 0; hh < NSPLIT; hh++) {
            const float4 v = *(const float4*)&d_Opart[((size_t)(hh * Bb + b) * Nn + m0 + ml) * Cc + cq * 4];
            a.x += v.x; a.y += v.y; a.z += v.z; a.w += v.w;
        }
        const float inv = sL[ml];
        s[cq * 4 + 0][ml] = a.x * inv;
        s[cq * 4 + 1][ml] = a.y * inv;
        s[cq * 4 + 2][ml] = a.z * inv;
        s[cq * 4 + 3][ml] = a.w * inv;
    }
    __syncthreads();

#pragma unroll
    for (int k = 0; k < 4; k++) {
        int e = tid + k * 256;
        int c = e >> 4, mq = e & 15;
        int gi = (b * Cc + c) * Nn + m0 + mq * 4;
        float4 xv = *(const float4*)&x[gi];
        float4 o;
        o.x = s[c][mq * 4 + 0] + xv.x;
        o.y = s[c][mq * 4 + 1] + xv.y;
        o.z = s[c][mq * 4 + 2] + xv.z;
        o.w = s[c][mq * 4 + 3] + xv.w;
        *(float4*)&out[gi] = o;
    }
}

// ---------------------------------------------------------------------------
extern "C" void kernel_launch(void* const* d_in, const int* in_sizes, int n_in,
                              void* d_out, int out_size)
{
    const float* x     = (const float*)d_in[0];
    const float* wq    = (const float*)d_in[1];
    const float* wk    = (const float*)d_in[2];
    const float* wv    = (const float*)d_in[3];
    const float* gamma = (const float*)d_in[4];
    float* out = (float*)d_out;
    (void)in_sizes; (void)n_in; (void)out_size;

    proj_kernel<<<dim3(Nn / 64, Bb), 256>>>(x, wq, wk, wv);
    attn_mma_kernel<<<dim3(Nn / MT, Bb, NSPLIT), 128>>>();
    combine_kernel<<<dim3(Nn / 64, Bb), 256>>>(x, gamma, out);
}